// round 1
// baseline (speedup 1.0000x reference)
#include <cuda_runtime.h>
#include <cuda_bf16.h>

// Problem constants
#define SEQ 4096
#define DIM 1024

// Scratch (allocation-free rule: __device__ globals)
__device__ float g_Q[SEQ * DIM];
__device__ float g_K[SEQ * DIM];
__device__ float g_V[SEQ * DIM];   // projected V, later scaled in-place by 1/rowsum
__device__ float g_E[(size_t)SEQ * SEQ];
__device__ float g_r[SEQ];

// ---------------------------------------------------------------------------
// Classic 128x128x8 SGEMM, 256 threads, 8x8 per-thread tile, float4 loads.
// TRANSB=false : B is [K,N] row-major.   TRANSB=true : B is [N,K] row-major.
// MODE 0: C = A@B + bias[n]
// MODE 1: C = exp((A@B)/1024)
// MODE 2: C = A@B
// ---------------------------------------------------------------------------
#define BM 128
#define BN 128
#define BK 8
#define TM 8
#define TN 8

template <bool TRANSB, int MODE>
__global__ __launch_bounds__(256, 2)
void sgemm_kernel(const float* __restrict__ A, const float* __restrict__ B,
                  const float* __restrict__ bias, float* __restrict__ C,
                  int M, int N, int K) {
    __shared__ float As[BK][BM];
    __shared__ float Bs[BK][BN];

    const int tid = threadIdx.x;
    const int bm = blockIdx.y * BM;
    const int bn = blockIdx.x * BN;

    const int trow = (tid >> 4) * TM;   // 0..120
    const int tcol = (tid & 15) * TN;   // 0..120

    float acc[TM][TN];
#pragma unroll
    for (int i = 0; i < TM; i++)
#pragma unroll
        for (int j = 0; j < TN; j++) acc[i][j] = 0.0f;

    // A-load indices: 128 rows x 8 k, one float4 per thread
    const int a_m = tid >> 1;
    const int a_k = (tid & 1) * 4;

    for (int k0 = 0; k0 < K; k0 += BK) {
        // ---- load A tile (transposed into As[k][m]) ----
        {
            float4 v = *reinterpret_cast<const float4*>(
                &A[(size_t)(bm + a_m) * K + (k0 + a_k)]);
            As[a_k + 0][a_m] = v.x;
            As[a_k + 1][a_m] = v.y;
            As[a_k + 2][a_m] = v.z;
            As[a_k + 3][a_m] = v.w;
        }
        // ---- load B tile ----
        if (TRANSB) {
            // B is [N,K]; tile: 128 n-rows x 8 k, transpose into Bs[k][n]
            const int b_n = tid >> 1;
            const int b_k = (tid & 1) * 4;
            float4 v = *reinterpret_cast<const float4*>(
                &B[(size_t)(bn + b_n) * K + (k0 + b_k)]);
            Bs[b_k + 0][b_n] = v.x;
            Bs[b_k + 1][b_n] = v.y;
            Bs[b_k + 2][b_n] = v.z;
            Bs[b_k + 3][b_n] = v.w;
        } else {
            // B is [K,N]; tile: 8 k-rows x 128 n, direct vector copy
            const int b_k = tid >> 5;
            const int b_n = (tid & 31) * 4;
            float4 v = *reinterpret_cast<const float4*>(
                &B[(size_t)(k0 + b_k) * N + (bn + b_n)]);
            *reinterpret_cast<float4*>(&Bs[b_k][b_n]) = v;
        }
        __syncthreads();

#pragma unroll
        for (int kk = 0; kk < BK; kk++) {
            float ra[TM], rb[TN];
            *reinterpret_cast<float4*>(&ra[0]) =
                *reinterpret_cast<const float4*>(&As[kk][trow]);
            *reinterpret_cast<float4*>(&ra[4]) =
                *reinterpret_cast<const float4*>(&As[kk][trow + 4]);
            *reinterpret_cast<float4*>(&rb[0]) =
                *reinterpret_cast<const float4*>(&Bs[kk][tcol]);
            *reinterpret_cast<float4*>(&rb[4]) =
                *reinterpret_cast<const float4*>(&Bs[kk][tcol + 4]);
#pragma unroll
            for (int i = 0; i < TM; i++)
#pragma unroll
                for (int j = 0; j < TN; j++)
                    acc[i][j] = fmaf(ra[i], rb[j], acc[i][j]);
        }
        __syncthreads();
    }

    // ---- epilogue ----
    float bv[TN];
    if (MODE == 0) {
#pragma unroll
        for (int j = 0; j < TN; j++) bv[j] = bias[bn + tcol + j];
    }
#pragma unroll
    for (int i = 0; i < TM; i++) {
        float outv[TN];
#pragma unroll
        for (int j = 0; j < TN; j++) {
            float v = acc[i][j];
            if (MODE == 0) v += bv[j];
            if (MODE == 1) v = __expf(v * (1.0f / 1024.0f));
            outv[j] = v;
        }
        float* crow = &C[(size_t)(bm + trow + i) * N + (bn + tcol)];
        *reinterpret_cast<float4*>(crow) =
            *reinterpret_cast<const float4*>(&outv[0]);
        *reinterpret_cast<float4*>(crow + 4) =
            *reinterpret_cast<const float4*>(&outv[4]);
    }
}

// ---------------------------------------------------------------------------
// Row-sum of E: one block per row
// ---------------------------------------------------------------------------
__global__ void rowsum_kernel(const float* __restrict__ E, float* __restrict__ r) {
    const int row = blockIdx.x;
    const float4* p = reinterpret_cast<const float4*>(E + (size_t)row * SEQ);
    float s = 0.0f;
    for (int i = threadIdx.x; i < SEQ / 4; i += 256) {
        float4 v = p[i];
        s += (v.x + v.y) + (v.z + v.w);
    }
    __shared__ float sm[8];
#pragma unroll
    for (int o = 16; o > 0; o >>= 1) s += __shfl_down_sync(0xFFFFFFFFu, s, o);
    if ((threadIdx.x & 31) == 0) sm[threadIdx.x >> 5] = s;
    __syncthreads();
    if (threadIdx.x < 8) {
        s = sm[threadIdx.x];
#pragma unroll
        for (int o = 4; o > 0; o >>= 1) s += __shfl_down_sync(0xFFu, s, o);
        if (threadIdx.x == 0) r[row] = s;
    }
}

// ---------------------------------------------------------------------------
// V'[j][d] = V[j][d] / r[j]   (in-place; V rewritten by proj each replay)
// ---------------------------------------------------------------------------
__global__ void scale_v_kernel(float* __restrict__ V, const float* __restrict__ r) {
    const int j = blockIdx.x;
    const float inv = 1.0f / r[j];
    float4* p = reinterpret_cast<float4*>(V + (size_t)j * DIM);
    float4 v = p[threadIdx.x];  // 256 threads * float4 = 1024 = DIM
    v.x *= inv; v.y *= inv; v.z *= inv; v.w *= inv;
    p[threadIdx.x] = v;
}

// ---------------------------------------------------------------------------
// Launch: query,key,value,Wq,bq,Wk,bk,Wv,bv  -> out [SEQ, DIM] fp32
// ---------------------------------------------------------------------------
extern "C" void kernel_launch(void* const* d_in, const int* in_sizes, int n_in,
                              void* d_out, int out_size) {
    const float* query = (const float*)d_in[0];
    const float* key   = (const float*)d_in[1];
    const float* value = (const float*)d_in[2];
    const float* Wq    = (const float*)d_in[3];
    const float* bq    = (const float*)d_in[4];
    const float* Wk    = (const float*)d_in[5];
    const float* bk    = (const float*)d_in[6];
    const float* Wv    = (const float*)d_in[7];
    const float* bv    = (const float*)d_in[8];
    float* out = (float*)d_out;

    float *Qp, *Kp, *Vp, *Ep, *rp;
    cudaGetSymbolAddress((void**)&Qp, g_Q);
    cudaGetSymbolAddress((void**)&Kp, g_K);
    cudaGetSymbolAddress((void**)&Vp, g_V);
    cudaGetSymbolAddress((void**)&Ep, g_E);
    cudaGetSymbolAddress((void**)&rp, g_r);

    dim3 block(256);
    dim3 gridProj(DIM / BN, SEQ / BM);   // 8 x 32
    dim3 gridScores(SEQ / BN, SEQ / BM); // 32 x 32
    dim3 gridOut(DIM / BN, SEQ / BM);    // 8 x 32

    // Projections: X @ W + b
    sgemm_kernel<false, 0><<<gridProj, block>>>(query, Wq, bq, Qp, SEQ, DIM, DIM);
    sgemm_kernel<false, 0><<<gridProj, block>>>(key,   Wk, bk, Kp, SEQ, DIM, DIM);
    sgemm_kernel<false, 0><<<gridProj, block>>>(value, Wv, bv, Vp, SEQ, DIM, DIM);

    // E = exp((Q @ K^T) / 1024)
    sgemm_kernel<true, 1><<<gridScores, block>>>(Qp, Kp, nullptr, Ep, SEQ, SEQ, DIM);

    // r[i] = sum_j E[i][j]
    rowsum_kernel<<<SEQ, block>>>(Ep, rp);

    // V'[j] = V[j] / r[j]
    scale_v_kernel<<<SEQ, block>>>(Vp, rp);

    // out = E @ V'
    sgemm_kernel<false, 2><<<gridOut, block>>>(Ep, Vp, nullptr, out, SEQ, DIM, SEQ);
}